// round 2
// baseline (speedup 1.0000x reference)
#include <cuda_runtime.h>
#include <math_constants.h>

// Problem geometry
#define NSRC 16384
#define NTAR 16384
#define NSPLIT 64                       // source splits
#define SRCB  (NSRC / NSPLIT)           // 256 sources per split
#define TB 8                            // target blocks
#define TAR_PER_BLOCK (NTAR / TB)       // 2048
#define NTHREADS 256
#define TPT 8                           // targets per thread (4 packed pairs)
#define NPAIR (TPT / 2)                 // 4
#define RED_BLOCKS (NTAR / NTHREADS)    // 64

// Scratch (allocation-free rule: __device__ globals)
__device__ float g_vmax[NSPLIT * NTAR];     // per-split per-target max of (t.s - 0.5||s||^2)
__device__ float g_partial[RED_BLOCKS];     // per-block partial sums

// ---- packed f32x2 helpers (FFMA2 only reachable via PTX) --------------------
__device__ __forceinline__ unsigned long long pk2(float a, float b) {
    unsigned long long r;
    asm("mov.b64 %0, {%1, %2};" : "=l"(r) : "f"(a), "f"(b));
    return r;
}
__device__ __forceinline__ unsigned long long ffma2(unsigned long long a,
                                                    unsigned long long b,
                                                    unsigned long long c) {
    unsigned long long d;
    asm("fma.rn.f32x2 %0, %1, %2, %3;" : "=l"(d) : "l"(a), "l"(b), "l"(c));
    return d;
}
__device__ __forceinline__ void upk2(unsigned long long v, float& lo, float& hi) {
    asm("mov.b64 {%0, %1}, %2;" : "=f"(lo), "=f"(hi) : "l"(v));
}

// ---------------------------------------------------------------------------
// Main pairwise pass. grid = (TB, NSPLIT), 256 threads.
// Block preps its own 256-source split into smem as DUPLICATED packed values:
//   s_ab[j] = (x, x, y, y)     s_cd[j] = (z, z, w, w)   with w = -0.5*||s||^2
// so the broadcast f32x2 operands come straight off LDS.128 (no dup MOVs).
// Inner loop per source per thread: 2 LDS.128 + 12 FFMA2 + 8 FMNMX.
// ---------------------------------------------------------------------------
__global__ __launch_bounds__(NTHREADS) void nn_main_kernel(const float* __restrict__ src,
                                                           const float* __restrict__ tar) {
    __shared__ float4 s_ab[SRCB];
    __shared__ float4 s_cd[SRCB];

    const int tb    = blockIdx.x;
    const int split = blockIdx.y;

    // In-block source prep (1 source per thread)
    {
        int g = split * SRCB + threadIdx.x;
        float x = src[3 * g + 0];
        float y = src[3 * g + 1];
        float z = src[3 * g + 2];
        float w = -0.5f * (x * x + y * y + z * z);
        s_ab[threadIdx.x] = make_float4(x, x, y, y);
        s_cd[threadIdx.x] = make_float4(z, z, w, w);
    }
    __syncthreads();

    const int t0 = tb * TAR_PER_BLOCK + threadIdx.x;

    // Pack 8 targets into 4 f32x2 lanes: pair (2p, 2p+1) = targets t0+2p*256, t0+(2p+1)*256
    unsigned long long txp[NPAIR], typ[NPAIR], tzp[NPAIR];
    float m[TPT];
#pragma unroll
    for (int p = 0; p < NPAIR; p++) {
        int ta = t0 + (2 * p) * NTHREADS;
        int tb2 = t0 + (2 * p + 1) * NTHREADS;
        txp[p] = pk2(tar[3 * ta + 0], tar[3 * tb2 + 0]);
        typ[p] = pk2(tar[3 * ta + 1], tar[3 * tb2 + 1]);
        tzp[p] = pk2(tar[3 * ta + 2], tar[3 * tb2 + 2]);
        m[2 * p]     = -CUDART_INF_F;
        m[2 * p + 1] = -CUDART_INF_F;
    }

#pragma unroll 4
    for (int j = 0; j < SRCB; j++) {
        float4 ab = s_ab[j];                 // (x, x, y, y)
        float4 cd = s_cd[j];                 // (z, z, w, w)
        unsigned long long xx = pk2(ab.x, ab.y);
        unsigned long long yy = pk2(ab.z, ab.w);
        unsigned long long zz = pk2(cd.x, cd.y);
        unsigned long long ww = pk2(cd.z, cd.w);
#pragma unroll
        for (int p = 0; p < NPAIR; p++) {
            // v = t.s - 0.5||s||^2  (packed over 2 targets)
            unsigned long long v = ffma2(tzp[p], zz, ww);
            v = ffma2(typ[p], yy, v);
            v = ffma2(txp[p], xx, v);
            float lo, hi;
            upk2(v, lo, hi);
            m[2 * p]     = fmaxf(m[2 * p], lo);
            m[2 * p + 1] = fmaxf(m[2 * p + 1], hi);
        }
    }

#pragma unroll
    for (int k = 0; k < TPT; k++)
        g_vmax[split * NTAR + t0 + k * NTHREADS] = m[k];
}

// ---------------------------------------------------------------------------
// Pass 2: combine splits, add 0.5*||t||^2, block-reduce (deterministic order)
// ---------------------------------------------------------------------------
__global__ __launch_bounds__(NTHREADS) void nn_reduce_kernel(const float* __restrict__ tar) {
    __shared__ float red[NTHREADS];
    const int t = blockIdx.x * NTHREADS + threadIdx.x;

    float vm = -CUDART_INF_F;
#pragma unroll
    for (int s = 0; s < NSPLIT; s++)
        vm = fmaxf(vm, g_vmax[s * NTAR + t]);

    float x = tar[3 * t + 0];
    float y = tar[3 * t + 1];
    float z = tar[3 * t + 2];
    // 0.5||t||^2 - max_s(t.s - 0.5||s||^2) == 0.5*min_s ||t - s||^2
    float c = fmaf(0.5f * x, x, fmaf(0.5f * y, y, fmaf(0.5f * z, z, -vm)));

    red[threadIdx.x] = c;
    __syncthreads();
#pragma unroll
    for (int stride = NTHREADS / 2; stride > 0; stride >>= 1) {
        if (threadIdx.x < stride)
            red[threadIdx.x] += red[threadIdx.x + stride];
        __syncthreads();
    }
    if (threadIdx.x == 0)
        g_partial[blockIdx.x] = red[0];
}

// ---------------------------------------------------------------------------
// Pass 3: fixed-order final sum (bitwise deterministic)
// ---------------------------------------------------------------------------
__global__ void nn_final_kernel(float* __restrict__ out) {
    if (threadIdx.x == 0) {
        float s = 0.0f;
        for (int i = 0; i < RED_BLOCKS; i++)
            s += g_partial[i];
        out[0] = s;
    }
}

extern "C" void kernel_launch(void* const* d_in, const int* in_sizes, int n_in,
                              void* d_out, int out_size) {
    const float* src = (const float*)d_in[0];   // src_V [16384,3]
    const float* tar = (const float*)d_in[1];   // tar_V [16384,3]
    float* out = (float*)d_out;

    dim3 grid(TB, NSPLIT);
    nn_main_kernel<<<grid, NTHREADS>>>(src, tar);
    nn_reduce_kernel<<<RED_BLOCKS, NTHREADS>>>(tar);
    nn_final_kernel<<<1, 32>>>(out);
}